// round 10
// baseline (speedup 1.0000x reference)
#include <cuda_runtime.h>
#include <cuda_fp16.h>
#include <cstdint>

// ---------------------------------------------------------------------------
// Fixed problem dims
// ---------------------------------------------------------------------------
static constexpr int M = 8192;
static constexpr int K = 4096;
static constexpr int N = 11008;

// Scratch: xh = fp16(x); wh = fp16(W + 2*B@A)
__device__ __half g_Xh[(size_t)M * K];
__device__ __half g_Wh[(size_t)N * K];

// ---------------------------------------------------------------------------
// Prologue 1: convert X to fp16
// ---------------------------------------------------------------------------
__global__ void conv_x_kernel(const float4* __restrict__ X, size_t n4) {
    size_t i = (size_t)blockIdx.x * blockDim.x + threadIdx.x;
    if (i >= n4) return;
    float4 v = X[i];
    __half2* Xh2 = reinterpret_cast<__half2*>(g_Xh);
    Xh2[2 * i]     = __floats2half2_rn(v.x, v.y);
    Xh2[2 * i + 1] = __floats2half2_rn(v.z, v.w);
}

// ---------------------------------------------------------------------------
// Prologue 2: Weff = W + 2.0*(B@A) -> fp16  (float4 loads, half2 stores)
// ---------------------------------------------------------------------------
static constexpr int FO = 32;
static constexpr int FI = 512;

__global__ void fold_w_kernel(const float* __restrict__ W,
                              const float* __restrict__ Bm,
                              const float* __restrict__ Am) {
    __shared__ float sA[16][FI];
    __shared__ float sB[FO][16];
    const int iBase = blockIdx.x * FI;
    const int oBase = blockIdx.y * FO;
    const int tid = threadIdx.x;

    for (int j = tid; j < 16 * FI; j += 256) {
        int r = j / FI, i = j % FI;
        sA[r][i] = Am[(size_t)r * K + iBase + i];
    }
    for (int j = tid; j < FO * 16; j += 256) {
        int o = j / 16, r = j % 16;
        sB[o][r] = Bm[(size_t)(oBase + o) * 16 + r];
    }
    __syncthreads();

    // Each thread handles 4 consecutive columns; FO*FI/4 = 4096 quads
    #pragma unroll
    for (int e = 0; e < (FO * FI) / (256 * 4); e++) {
        int q = tid + 256 * e;                // quad index
        int oo = (q * 4) / FI, ii = (q * 4) % FI;
        size_t g = (size_t)(oBase + oo) * K + iBase + ii;
        float4 w4 = *reinterpret_cast<const float4*>(W + g);
        float a0 = w4.x, a1 = w4.y, a2 = w4.z, a3 = w4.w;
        #pragma unroll
        for (int r = 0; r < 16; r++) {
            float b2 = 2.0f * sB[oo][r];
            a0 += b2 * sA[r][ii];
            a1 += b2 * sA[r][ii + 1];
            a2 += b2 * sA[r][ii + 2];
            a3 += b2 * sA[r][ii + 3];
        }
        __half2* dst = reinterpret_cast<__half2*>(g_Wh + g);
        dst[0] = __floats2half2_rn(a0, a1);
        dst[1] = __floats2half2_rn(a2, a3);
    }
}

// ---------------------------------------------------------------------------
// Main GEMM: C = Xh@Wh^T + bias  (single-pass fp16, fp32 accumulate)
// R4-structure clone: CTA 128x128, 8 warps (2x4), warp 64x32, scalar-LDS
// fragments, 2-stage cp.async, double sync. Changes vs R4: BK=64 (64 MMAs
// per warp-stage) and DUAL accumulator chains (even/odd kk interleaved).
// LDT=72 halves (144B rows): bank walk 36r mod 32 = 4r -> conflict-free.
// ---------------------------------------------------------------------------
static constexpr int BM = 128, BN = 128, BK = 64;
static constexpr int TM_TILES = M / BM;   // 64
static constexpr int TN_TILES = N / BN;   // 86
static constexpr int NSTAGES_K = K / BK;  // 64

static constexpr int LDT = BK + 8;                    // 72 halves = 144B
static constexpr int TILE_ELEMS = BM * LDT;           // 9216 halves
static constexpr int STAGE_ELEMS = 2 * TILE_ELEMS;    // xh, wh
static constexpr int SMEM_BYTES = 2 * STAGE_ELEMS * (int)sizeof(__half); // 73728

#define MMA_FP16(d, a, b)                                                      \
    asm volatile(                                                              \
        "mma.sync.aligned.m16n8k16.row.col.f32.f16.f16.f32 "                   \
        "{%0,%1,%2,%3}, {%4,%5,%6,%7}, {%8,%9}, {%0,%1,%2,%3};"                \
        : "+f"((d)[0]), "+f"((d)[1]), "+f"((d)[2]), "+f"((d)[3])               \
        : "r"((a)[0]), "r"((a)[1]), "r"((a)[2]), "r"((a)[3]),                  \
          "r"((b)[0]), "r"((b)[1]))

__device__ __forceinline__ void cp16(uint32_t sdst, const void* g) {
    asm volatile("cp.async.cg.shared.global [%0], [%1], 16;" :: "r"(sdst), "l"(g));
}
#define CP_COMMIT() asm volatile("cp.async.commit_group;" ::: "memory")
#define CP_WAIT(n) asm volatile("cp.async.wait_group %0;" :: "n"(n) : "memory")

__device__ __forceinline__ void issue_stage(__half* st, int k0,
                                            int mBase, int nBase, int tid) {
    const __half* srcs[2] = {g_Xh + (size_t)mBase * K, g_Wh + (size_t)nBase * K};
    // each tile: 128 rows x 8 16B-chunks = 1024 chunks; 2048 total, 8/thread
    #pragma unroll
    for (int j = 0; j < 8; j++) {
        int c = tid + 256 * j;
        int t2 = c >> 10;            // 0: X, 1: W
        int idx = c & 1023;
        int row = idx >> 3;
        int col16 = idx & 7;
        const __half* g = srcs[t2] + (size_t)row * K + k0 + col16 * 8;
        __half* sdst = st + t2 * TILE_ELEMS + row * LDT + col16 * 8;
        cp16((uint32_t)__cvta_generic_to_shared(sdst), g);
    }
    CP_COMMIT();
}

// Load one kk-step's fragments (scalar LDS, R4 addressing, LDT=72)
__device__ __forceinline__ void load_frags(const __half* Xhs, const __half* Whs,
                                           int kk, int wm, int wn, int lane,
                                           uint32_t a[4][4], uint32_t b[4][2]) {
    const int qrow = lane >> 2;
    const int qk = (lane & 3) * 2;
    const int kb = kk * 16 + qk;
    #pragma unroll
    for (int nt = 0; nt < 4; nt++) {
        int n0 = wn * 32 + nt * 8 + qrow;
        b[nt][0] = *(const uint32_t*)(Whs + n0 * LDT + kb);
        b[nt][1] = *(const uint32_t*)(Whs + n0 * LDT + kb + 8);
    }
    #pragma unroll
    for (int mt = 0; mt < 4; mt++) {
        int m0 = wm * 64 + mt * 16 + qrow;
        a[mt][0] = *(const uint32_t*)(Xhs + m0 * LDT + kb);
        a[mt][1] = *(const uint32_t*)(Xhs + (m0 + 8) * LDT + kb);
        a[mt][2] = *(const uint32_t*)(Xhs + m0 * LDT + kb + 8);
        a[mt][3] = *(const uint32_t*)(Xhs + (m0 + 8) * LDT + kb + 8);
    }
}

__device__ __forceinline__ void compute_stage(const __half* st, int wm, int wn,
                                              int lane,
                                              float accE[4][4][4],
                                              float accO[4][4][4]) {
    const __half* Xhs = st;
    const __half* Whs = st + TILE_ELEMS;
    #pragma unroll
    for (int kp = 0; kp < 2; kp++) {   // kk pairs (0,1) and (2,3)
        uint32_t a0[4][4], b0[4][2], a1[4][4], b1[4][2];
        load_frags(Xhs, Whs, 2 * kp,     wm, wn, lane, a0, b0);
        load_frags(Xhs, Whs, 2 * kp + 1, wm, wn, lane, a1, b1);
        #pragma unroll
        for (int mt = 0; mt < 4; mt++) {
            #pragma unroll
            for (int nt = 0; nt < 4; nt++) {
                MMA_FP16(accE[mt][nt], a0[mt], b0[nt]);   // chain E (even kk)
                MMA_FP16(accO[mt][nt], a1[mt], b1[nt]);   // chain O (odd kk)
            }
        }
    }
}

__global__ __launch_bounds__(256, 1)
void gemm_fp16_kernel(const float* __restrict__ bias, float* __restrict__ C) {
    extern __shared__ __half smem[];
    const int tid = threadIdx.x;
    const int warp = tid >> 5;
    const int lane = tid & 31;
    const int wm = warp >> 2;  // 0..1
    const int wn = warp & 3;   // 0..3

    // Supertile raster: groups of 16 N-tiles, M-major within each group
    int lin = blockIdx.x;
    int gid = lin >> 10;            // / (16*64)
    int rem = lin & 1023;
    int n0 = gid * 16;
    int width = min(16, TN_TILES - n0);
    int mT = rem / width;
    int nT = n0 + rem % width;
    const int mBase = mT * BM;
    const int nBase = nT * BN;

    float accE[4][4][4], accO[4][4][4];
    #pragma unroll
    for (int a = 0; a < 4; a++)
        #pragma unroll
        for (int b = 0; b < 4; b++)
            #pragma unroll
            for (int c = 0; c < 4; c++) { accE[a][b][c] = 0.0f; accO[a][b][c] = 0.0f; }

    issue_stage(smem, 0, mBase, nBase, tid);

    for (int s = 0; s < NSTAGES_K; s++) {
        if (s + 1 < NSTAGES_K) {
            issue_stage(smem + ((s + 1) & 1) * STAGE_ELEMS, (s + 1) * BK,
                        mBase, nBase, tid);
            CP_WAIT(1);
        } else {
            CP_WAIT(0);
        }
        __syncthreads();
        compute_stage(smem + (s & 1) * STAGE_ELEMS, wm, wn, lane, accE, accO);
        __syncthreads();
    }

    // Epilogue: merge chains, add bias, write fp32
    const int qrow = lane >> 2;
    const int qc = (lane & 3) * 2;
    #pragma unroll
    for (int nt = 0; nt < 4; nt++) {
        int col = nBase + wn * 32 + nt * 8 + qc;
        float2 bs = *(const float2*)(bias + col);
        #pragma unroll
        for (int mt = 0; mt < 4; mt++) {
            int row = mBase + wm * 64 + mt * 16 + qrow;
            float2 v0, v1;
            v0.x = accE[mt][nt][0] + accO[mt][nt][0] + bs.x;
            v0.y = accE[mt][nt][1] + accO[mt][nt][1] + bs.y;
            v1.x = accE[mt][nt][2] + accO[mt][nt][2] + bs.x;
            v1.y = accE[mt][nt][3] + accO[mt][nt][3] + bs.y;
            *(float2*)(C + (size_t)row * N + col) = v0;
            *(float2*)(C + (size_t)(row + 8) * N + col) = v1;
        }
    }
}

// ---------------------------------------------------------------------------
// Launch
// ---------------------------------------------------------------------------
extern "C" void kernel_launch(void* const* d_in, const int* in_sizes, int n_in,
                              void* d_out, int out_size) {
    const float* x    = (const float*)d_in[0];
    const float* W    = (const float*)d_in[1];
    const float* bias = (const float*)d_in[2];
    const float* B    = (const float*)d_in[3];
    const float* A    = (const float*)d_in[4];
    float* out = (float*)d_out;

    size_t n4 = (size_t)M * K / 4;
    conv_x_kernel<<<(unsigned)((n4 + 255) / 256), 256>>>((const float4*)x, n4);
    fold_w_kernel<<<dim3(K / FI, N / FO), 256>>>(W, B, A);

    cudaFuncSetAttribute(gemm_fp16_kernel,
                         cudaFuncAttributeMaxDynamicSharedMemorySize, SMEM_BYTES);
    gemm_fp16_kernel<<<TM_TILES * TN_TILES, 256, SMEM_BYTES>>>(bias, out);
}

// round 11
// speedup vs baseline: 1.0746x; 1.0746x over previous
#include <cuda_runtime.h>
#include <cuda_fp16.h>
#include <cstdint>

// ---------------------------------------------------------------------------
// Fixed problem dims
// ---------------------------------------------------------------------------
static constexpr int M = 8192;
static constexpr int K = 4096;
static constexpr int N = 11008;

// Scratch: xh = fp16(x); wh = fp16(W + 2*B@A)
__device__ __half g_Xh[(size_t)M * K];
__device__ __half g_Wh[(size_t)N * K];

// ---------------------------------------------------------------------------
// Fused prologue: blocks [0, FOLD_BLOCKS) fold W; the rest convert X.
// ---------------------------------------------------------------------------
static constexpr int FO = 32;
static constexpr int FI = 512;
static constexpr int FOLD_BX = K / FI;            // 8
static constexpr int FOLD_BY = N / FO;            // 344
static constexpr int FOLD_BLOCKS = FOLD_BX * FOLD_BY;   // 2752
static constexpr int CONV_N4 = M * K / 4;         // 8388608 float4s
static constexpr int CONV_BLOCKS = CONV_N4 / 256; // 32768
static constexpr int PRO_BLOCKS = FOLD_BLOCKS + CONV_BLOCKS;

__global__ __launch_bounds__(256)
void prologue_kernel(const float* __restrict__ X,
                     const float* __restrict__ W,
                     const float* __restrict__ Bm,
                     const float* __restrict__ Am) {
    const int tid = threadIdx.x;
    if (blockIdx.x >= FOLD_BLOCKS) {
        // ---- convert X to fp16 (DRAM-bound) ----
        size_t i = (size_t)(blockIdx.x - FOLD_BLOCKS) * 256 + tid;
        float4 v = reinterpret_cast<const float4*>(X)[i];
        __half2* Xh2 = reinterpret_cast<__half2*>(g_Xh);
        Xh2[2 * i]     = __floats2half2_rn(v.x, v.y);
        Xh2[2 * i + 1] = __floats2half2_rn(v.z, v.w);
        return;
    }

    // ---- fold W: Weff = W + 2*(B@A) -> fp16 ----
    __shared__ float sA[16][FI];
    __shared__ float sB[FO][16];
    const int bx = blockIdx.x % FOLD_BX;
    const int by = blockIdx.x / FOLD_BX;
    const int iBase = bx * FI;
    const int oBase = by * FO;

    for (int j = tid; j < 16 * FI; j += 256) {
        int r = j / FI, i = j % FI;
        sA[r][i] = Am[(size_t)r * K + iBase + i];
    }
    for (int j = tid; j < FO * 16; j += 256) {
        int o = j / 16, r = j % 16;
        sB[o][r] = Bm[(size_t)(oBase + o) * 16 + r];
    }
    __syncthreads();

    #pragma unroll
    for (int e = 0; e < (FO * FI) / (256 * 4); e++) {
        int q = tid + 256 * e;
        int oo = (q * 4) / FI, ii = (q * 4) % FI;
        size_t g = (size_t)(oBase + oo) * K + iBase + ii;
        float4 w4 = *reinterpret_cast<const float4*>(W + g);
        float a0 = w4.x, a1 = w4.y, a2 = w4.z, a3 = w4.w;
        #pragma unroll
        for (int r = 0; r < 16; r++) {
            float b2 = 2.0f * sB[oo][r];
            a0 += b2 * sA[r][ii];
            a1 += b2 * sA[r][ii + 1];
            a2 += b2 * sA[r][ii + 2];
            a3 += b2 * sA[r][ii + 3];
        }
        __half2* dst = reinterpret_cast<__half2*>(g_Wh + g);
        dst[0] = __floats2half2_rn(a0, a1);
        dst[1] = __floats2half2_rn(a2, a3);
    }
}

// ---------------------------------------------------------------------------
// Main GEMM (R6 exact): C = Xh@Wh^T + bias  (single-pass fp16, fp32 accum)
// CTA 128x128, warp 64x32 (8 warps 2x4), BK=64, ldmatrix.x4, 3-stage cp.async.
// SMEM rows: 64 halves = 128B data + 16B pad = 144B stride; 144*i mod 128
// covers all 8 16B-phases -> conflict-free ldmatrix + cp.async stores.
// ---------------------------------------------------------------------------
static constexpr int BM = 128, BN = 128, BK = 64;
static constexpr int TM_TILES = M / BM;   // 64
static constexpr int TN_TILES = N / BN;   // 86
static constexpr int NSTAGES_K = K / BK;  // 64

static constexpr int ROWB = 144;
static constexpr int TILE_X = BM * ROWB;              // 18432
static constexpr int TILE_W = BN * ROWB;              // 18432
static constexpr int OFF_X = 0;
static constexpr int OFF_W = TILE_X;
static constexpr int STAGE_BYTES = TILE_X + TILE_W;   // 36864
static constexpr int NSLOTS = 3;
static constexpr int SMEM_TOTAL = NSLOTS * STAGE_BYTES;  // 110592 (108KB)

#define MMA_FP16(d, a, b)                                                      \
    asm volatile(                                                              \
        "mma.sync.aligned.m16n8k16.row.col.f32.f16.f16.f32 "                   \
        "{%0,%1,%2,%3}, {%4,%5,%6,%7}, {%8,%9}, {%0,%1,%2,%3};"                \
        : "+f"((d)[0]), "+f"((d)[1]), "+f"((d)[2]), "+f"((d)[3])               \
        : "r"((a)[0]), "r"((a)[1]), "r"((a)[2]), "r"((a)[3]),                  \
          "r"((b)[0]), "r"((b)[1]))

#define LDSM_X4(r0, r1, r2, r3, addr)                                          \
    asm volatile("ldmatrix.sync.aligned.m8n8.x4.shared.b16 {%0,%1,%2,%3}, [%4];" \
                 : "=r"(r0), "=r"(r1), "=r"(r2), "=r"(r3) : "r"(addr))

__device__ __forceinline__ void cp16(uint32_t sdst, const void* g) {
    asm volatile("cp.async.cg.shared.global [%0], [%1], 16;" :: "r"(sdst), "l"(g));
}
#define CP_COMMIT() asm volatile("cp.async.commit_group;" ::: "memory")
#define CP_WAIT(n) asm volatile("cp.async.wait_group %0;" :: "n"(n) : "memory")

__device__ __forceinline__ void issue_stage(uint32_t tb, int k0,
                                            const __half* gX, const __half* gW,
                                            int tid) {
    #pragma unroll
    for (int j = 0; j < 4; j++) {
        int q = tid + 256 * j;
        int r = q >> 3, c = q & 7;
        cp16(tb + OFF_X + r * ROWB + c * 16, gX + (size_t)r * K + k0 + c * 8);
    }
    #pragma unroll
    for (int j = 0; j < 4; j++) {
        int q = tid + 256 * j;
        int r = q >> 3, c = q & 7;
        cp16(tb + OFF_W + r * ROWB + c * 16, gW + (size_t)r * K + k0 + c * 8);
    }
    CP_COMMIT();
}

__device__ __forceinline__ void compute_stage(uint32_t tb, int wm, int wn, int lane,
                                              float acc[4][4][4]) {
    const int lrow = lane & 15;
    const int lcol = lane >> 4;
    #pragma unroll
    for (int kk = 0; kk < 4; kk++) {
        const uint32_t kbyte = kk * 32 + lcol * 16;

        uint32_t bh[4][2];
        #pragma unroll
        for (int np = 0; np < 2; np++) {
            uint32_t base = tb + OFF_W + (wn * 32 + np * 16 + lrow) * ROWB + kbyte;
            uint32_t t0, t1, t2, t3;
            LDSM_X4(t0, t1, t2, t3, base);
            bh[2 * np][0] = t0; bh[2 * np + 1][0] = t1;
            bh[2 * np][1] = t2; bh[2 * np + 1][1] = t3;
        }

        #pragma unroll
        for (int mt = 0; mt < 4; mt++) {
            uint32_t base = tb + OFF_X + (wm * 64 + mt * 16 + lrow) * ROWB + kbyte;
            uint32_t ah[4];
            LDSM_X4(ah[0], ah[1], ah[2], ah[3], base);
            #pragma unroll
            for (int nt = 0; nt < 4; nt++) {
                MMA_FP16(acc[mt][nt], ah, bh[nt]);
            }
        }
    }
}

__global__ __launch_bounds__(256, 2)
void gemm_fp16_kernel(const float* __restrict__ bias, float* __restrict__ C) {
    extern __shared__ __align__(1024) char smem[];
    uint32_t sb;
    asm("{ .reg .u64 t; cvta.to.shared.u64 t, %1; cvt.u32.u64 %0, t; }"
        : "=r"(sb) : "l"(smem));

    const int tid = threadIdx.x;
    const int warp = tid >> 5;
    const int lane = tid & 31;
    const int wm = warp >> 2;  // 0..1
    const int wn = warp & 3;   // 0..3

    // Supertile raster: groups of 16 N-tiles, M-major within each group
    int lin = blockIdx.x;
    int gid = lin >> 10;            // / (16*64)
    int rem = lin & 1023;
    int n0 = gid * 16;
    int width = min(16, TN_TILES - n0);
    int mT = rem / width;
    int nT = n0 + rem % width;
    const int mBase = mT * BM;
    const int nBase = nT * BN;

    const __half* gX = g_Xh + (size_t)mBase * K;
    const __half* gW = g_Wh + (size_t)nBase * K;

    float acc[4][4][4];
    #pragma unroll
    for (int a = 0; a < 4; a++)
        #pragma unroll
        for (int b = 0; b < 4; b++)
            #pragma unroll
            for (int c = 0; c < 4; c++) acc[a][b][c] = 0.0f;

    issue_stage(sb + 0 * STAGE_BYTES, 0 * BK, gX, gW, tid);
    issue_stage(sb + 1 * STAGE_BYTES, 1 * BK, gX, gW, tid);

    int slot = 0;
    for (int s = 0; s < NSTAGES_K; s++) {
        if (s + 2 < NSTAGES_K) {
            int wslot = slot - 1;
            if (wslot < 0) wslot += NSLOTS;
            issue_stage(sb + wslot * STAGE_BYTES, (s + 2) * BK, gX, gW, tid);
            CP_WAIT(2);
        } else if (s + 1 < NSTAGES_K) {
            CP_WAIT(1);
        } else {
            CP_WAIT(0);
        }
        __syncthreads();
        compute_stage(sb + slot * STAGE_BYTES, wm, wn, lane, acc);
        __syncthreads();
        slot++;
        if (slot == NSLOTS) slot = 0;
    }

    // Epilogue: add bias, write fp32
    const int qrow = lane >> 2;
    const int qc = (lane & 3) * 2;
    #pragma unroll
    for (int nt = 0; nt < 4; nt++) {
        int col = nBase + wn * 32 + nt * 8 + qc;
        float2 bs = *(const float2*)(bias + col);
        #pragma unroll
        for (int mt = 0; mt < 4; mt++) {
            int row = mBase + wm * 64 + mt * 16 + qrow;
            float2 v0 = make_float2(acc[mt][nt][0] + bs.x, acc[mt][nt][1] + bs.y);
            float2 v1 = make_float2(acc[mt][nt][2] + bs.x, acc[mt][nt][3] + bs.y);
            *(float2*)(C + (size_t)row * N + col) = v0;
            *(float2*)(C + (size_t)(row + 8) * N + col) = v1;
        }
    }
}

// ---------------------------------------------------------------------------
// Launch
// ---------------------------------------------------------------------------
extern "C" void kernel_launch(void* const* d_in, const int* in_sizes, int n_in,
                              void* d_out, int out_size) {
    const float* x    = (const float*)d_in[0];
    const float* W    = (const float*)d_in[1];
    const float* bias = (const float*)d_in[2];
    const float* B    = (const float*)d_in[3];
    const float* A    = (const float*)d_in[4];
    float* out = (float*)d_out;

    prologue_kernel<<<PRO_BLOCKS, 256>>>(x, W, B, A);

    cudaFuncSetAttribute(gemm_fp16_kernel,
                         cudaFuncAttributeMaxDynamicSharedMemorySize, SMEM_TOTAL);
    gemm_fp16_kernel<<<TM_TILES * TN_TILES, 256, SMEM_TOTAL>>>(bias, out);
}